// round 12
// baseline (speedup 1.0000x reference)
#include <cuda_runtime.h>
#include <math.h>

// Problem constants
#define BB   32
#define SS   1024
#define DD   3
#define NF   512
#define NS   64
#define HID  100
#define FSZ  256

// Decomposition
#define NSC  16           // S chunks
#define SCH  (SS/NSC)     // 64 steps per chunk

// Scratch (device globals: allocation-free per harness rules)
__device__ float g_Womg[NF*3];
__device__ float g_totC[BB*NSC*NF];
__device__ float g_totS[BB*NSC*NF];

// Warp-wide float add reduction (SHFL butterfly; redux.f32 unavailable on
// the compute_103 PTX target).
__device__ __forceinline__ float warp_sum(float v) {
    #pragma unroll
    for (int o = 16; o; o >>= 1) v += __shfl_xor_sync(0xffffffffu, v, o);
    return v;
}

// ---------------- Fused Fourier-feature MLP ----------------
// R11 evidence: NOT occupancy-bound (76.6% occ gave no speedup) — bound by
// the W2 LDG->FMA dependency chain (L1=28.4% tallest counter, 1 LDG per
// 2 FLOP). Fix: batch F=2 fourier samples per block so each W2 load feeds
// 2 FMAs into 4 independent accumulator chains. 256 blocks x 512 threads.

#define FB 2   // fourier samples per block

__global__ void __launch_bounds__(512) k_mlp(const float* __restrict__ noise,
                                             const float* __restrict__ W1,
                                             const float* __restrict__ b1,
                                             const float* __restrict__ W2,
                                             const float* __restrict__ b2,
                                             const float* __restrict__ W) {
    int f0 = blockIdx.x * FB;
    int t  = threadIdx.x;

    __shared__ float s_noise[FB][NS];
    __shared__ float s_h[FB][HID];
    __shared__ float s_acc[FB][2][FSZ];
    __shared__ float s_red[16][3];

    if (t < FB*NS) s_noise[t/NS][t%NS] = noise[f0*NS + t];
    __syncthreads();

    // hidden: 2 samples x 100 units on threads 0..199, two subaccumulators
    if (t < FB*HID) {
        int fl = t / HID, j = t % HID;
        const float* nz = s_noise[fl];
        float a0 = 0.f, a1 = 0.f;
        #pragma unroll 8
        for (int k = 0; k < NS; k += 2) {
            a0 = fmaf(nz[k],   W1[k*HID + j],     a0);
            a1 = fmaf(nz[k+1], W1[(k+1)*HID + j], a1);
        }
        s_h[fl][j] = tanhf(b1[j] + a0 + a1);
    }
    __syncthreads();

    // fourier: col = t&255, jhalf = t>>8. Each W2 load feeds both samples;
    // j-parity split gives 4 independent FMA chains of 25.
    {
        int col = t & 255;
        int jb  = (t >> 8) * 50;
        float a00 = 0.f, a01 = 0.f, a10 = 0.f, a11 = 0.f;
        #pragma unroll 5
        for (int j = 0; j < 50; j += 2) {
            float wa = W2[(jb+j)*FSZ   + col];
            float wb = W2[(jb+j+1)*FSZ + col];
            float h0a = s_h[0][jb+j], h0b = s_h[0][jb+j+1];
            float h1a = s_h[1][jb+j], h1b = s_h[1][jb+j+1];
            a00 = fmaf(h0a, wa, a00);
            a01 = fmaf(h0b, wb, a01);
            a10 = fmaf(h1a, wa, a10);
            a11 = fmaf(h1b, wb, a11);
        }
        s_acc[0][t>>8][col] = a00 + a01;
        s_acc[1][t>>8][col] = a10 + a11;
    }
    __syncthreads();

    // combine halves, tanh, Womg reduction.
    // threads 0..255 -> sample 0 (warps 0-7), 256..511 -> sample 1 (warps 8-15)
    {
        int fl = t >> 8, col = t & 255;
        float fs = tanhf(b2[col] + s_acc[fl][0][col] + s_acc[fl][1][col]);
        float p0 = fs * W[col*3+0];
        float p1 = fs * W[col*3+1];
        float p2 = fs * W[col*3+2];
        p0 = warp_sum(p0); p1 = warp_sum(p1); p2 = warp_sum(p2);
        int lane = t & 31, warp = t >> 5;
        if (lane == 0) {
            s_red[warp][0] = p0; s_red[warp][1] = p1; s_red[warp][2] = p2;
        }
    }
    __syncthreads();
    if (t < FB*3) {
        int fl = t / 3, d = t % 3;
        float v = 0.f;
        #pragma unroll
        for (int w = 0; w < 8; w++) v += s_red[fl*8 + w][d];
        g_Womg[(f0 + fl)*3 + d] = v;
    }
}

// ---------------- Pass A: per-S-chunk trig totals ----------------
// 512 threads = all NF features; grid (NSC, BB).

__global__ void __launch_bounds__(512) k_passA(const float* __restrict__ X) {
    int t  = threadIdx.x;            // n = t
    int sc = blockIdx.x, b = blockIdx.y;
    float w0 = g_Womg[t*3+0], w1 = g_Womg[t*3+1], w2 = g_Womg[t*3+2];

    __shared__ float sx[SCH*3];
    int s0 = sc*SCH;
    const float* xp = X + ((size_t)b*SS + s0)*3;
    if (t < SCH*3) sx[t] = xp[t];
    __syncthreads();

    float sumC = 0.f, sumS = 0.f;
    #pragma unroll 8
    for (int k = 0; k < SCH; k++) {
        float th = fmaf(sx[k*3+2], w2, fmaf(sx[k*3+1], w1, sx[k*3]*w0));
        float sv, cv;
        __sincosf(th, &sv, &cv);
        sumC += cv; sumS += sv;
    }
    g_totC[(b*NSC + sc)*NF + t] = sumC;
    g_totS[(b*NSC + sc)*NF + t] = sumS;
}

// ---------------- Pass C fused with final output ----------------
// Same grid/block as passA. All 16 warp-partials per step stay in smem;
// block reduces them and writes lam + loglik directly.

__global__ void __launch_bounds__(512) k_passCF(const float* __restrict__ X,
                                                const float* __restrict__ alpha,
                                                float* __restrict__ out) {
    int t  = threadIdx.x;            // n = t
    int sc = blockIdx.x, b = blockIdx.y;
    float w0 = g_Womg[t*3+0], w1 = g_Womg[t*3+1], w2 = g_Womg[t*3+2];

    // exclusive offsets from preceding S chunks
    float runC = 0.f, runS = 0.f;
    for (int p = 0; p < sc; p++) {
        runC += g_totC[(b*NSC + p)*NF + t];
        runS += g_totS[(b*NSC + p)*NF + t];
    }

    __shared__ float sx[SCH*3];
    __shared__ float s_red[SCH][17];   // +1 pad: conflict-free tail reads
    int s0 = sc*SCH;
    const float* xp = X + ((size_t)b*SS + s0)*3;
    if (t < SCH*3) sx[t] = xp[t];
    __syncthreads();

    int lane = t & 31, warp = t >> 5;

    #pragma unroll 4
    for (int k = 0; k < SCH; k++) {
        float th = fmaf(sx[k*3+2], w2, fmaf(sx[k*3+1], w1, sx[k*3]*w0));
        float sv, cv;
        __sincosf(th, &sv, &cv);
        float contrib = cv*runC + sv*runS;   // EXCLUSIVE prefix
        runC += cv; runS += sv;
        contrib = warp_sum(contrib);
        if (lane == 0) s_red[k][warp] = contrib;
    }
    __syncthreads();

    if (t < SCH) {
        float s = 0.f;
        #pragma unroll
        for (int i = 0; i < 16; i++) s += s_red[t][i];
        float lam = fmaf(alpha[0], s * (1.0f/NF), 10.0f);
        int sg = s0 + t;
        out[b*SS + sg] = lam;

        float x0 = sx[t*3];
        float mask = (x0 > 0.f) ? 1.f : 0.f;
        const float C2 = -3947.8417604357433f;   // -MU*T*(2*pi)^(D-1)
        out[BB*SS + b*(SS+1) + sg] = logf(lam)*mask + C2;
    }
    if (sc == 0 && t == 0) {
        const float C2 = -3947.8417604357433f;
        out[BB*SS + b*(SS+1) + SS] = C2;         // extra (S+1)-th column
    }
}

// ---------------- Launch ----------------

extern "C" void kernel_launch(void* const* d_in, const int* in_sizes, int n_in,
                              void* d_out, int out_size) {
    const float* X     = (const float*)d_in[0];
    const float* noise = (const float*)d_in[1];
    const float* W1    = (const float*)d_in[2];
    const float* b1    = (const float*)d_in[3];
    const float* W2    = (const float*)d_in[4];
    const float* b2    = (const float*)d_in[5];
    const float* W     = (const float*)d_in[6];
    const float* alpha = (const float*)d_in[7];
    float* out = (float*)d_out;

    k_mlp<<<NF/FB, 512>>>(noise, W1, b1, W2, b2, W);

    dim3 grid(NSC, BB);
    k_passA <<<grid, 512>>>(X);
    k_passCF<<<grid, 512>>>(X, alpha, out);
}

// round 13
// speedup vs baseline: 1.0059x; 1.0059x over previous
#include <cuda_runtime.h>
#include <math.h>

// Problem constants
#define BB   32
#define SS   1024
#define DD   3
#define NF   512
#define NS   64
#define HID  100
#define FSZ  256

// Decomposition
#define NSC  16           // S chunks
#define SCH  (SS/NSC)     // 64 steps per chunk

// Scratch (device globals: allocation-free per harness rules)
__device__ float g_Womg[NF*3];
__device__ float g_totC[BB*NSC*NF];
__device__ float g_totS[BB*NSC*NF];

// Warp-wide float add reduction (SHFL butterfly; redux.f32 unavailable on
// the compute_103 PTX target).
__device__ __forceinline__ float warp_sum(float v) {
    #pragma unroll
    for (int o = 16; o; o >>= 1) v += __shfl_xor_sync(0xffffffffu, v, o);
    return v;
}

// ---------------- Fused Fourier-feature MLP ----------------
// R11 structure (measured best: 12.7us) + ILP fix. Evidence: not traffic-
// bound (DRAM<0.5%, L2<3%), not occupancy-bound (76.6% occ, issue 27%).
// Bound by per-thread memory-level parallelism: regs=32 allows ~4 in-flight
// loads, so 50 LDG+LDS pairs serialize on L1 latency. Fix: allow 128 regs
// (__launch_bounds__(512,1)) + fully unroll so ptxas front-batches loads.

__global__ void __launch_bounds__(512, 1) k_mlp(const float* __restrict__ noise,
                                                const float* __restrict__ W1,
                                                const float* __restrict__ b1,
                                                const float* __restrict__ W2,
                                                const float* __restrict__ b2,
                                                const float* __restrict__ W) {
    int f = blockIdx.x;
    int t = threadIdx.x;
    int tl   = t & 255;      // col / hidden-unit id
    int half = t >> 8;       // 0 or 1: which j/k half this thread owns

    __shared__ float s_noise[NS];
    __shared__ float s_hp[2][HID];    // hidden k-partials
    __shared__ float s_h[HID];
    __shared__ float s_acc[512];      // fourier j-partials
    __shared__ float s_red[8][3];

    if (t < NS) s_noise[t] = noise[f*NS + t];
    __syncthreads();

    // hidden partials: h[j] over k in [half*32, half*32+32), fully unrolled
    if (tl < HID) {
        int k0 = half * 32;
        float a0 = 0.f, a1 = 0.f, a2 = 0.f, a3 = 0.f;
        #pragma unroll
        for (int k = 0; k < 32; k += 4) {
            a0 = fmaf(s_noise[k0+k],   W1[(k0+k)*HID + tl],   a0);
            a1 = fmaf(s_noise[k0+k+1], W1[(k0+k+1)*HID + tl], a1);
            a2 = fmaf(s_noise[k0+k+2], W1[(k0+k+2)*HID + tl], a2);
            a3 = fmaf(s_noise[k0+k+3], W1[(k0+k+3)*HID + tl], a3);
        }
        s_hp[half][tl] = (a0 + a1) + (a2 + a3);
    }
    __syncthreads();
    if (t < HID)
        s_h[t] = tanhf(b1[t] + s_hp[0][t] + s_hp[1][t]);
    __syncthreads();

    // fourier partials: col = tl, j in [half*50, half*50+50).
    // Fully unrolled; 4 independent accumulator chains; generous register
    // budget lets ptxas batch the W2 loads (MLP >> 4).
    {
        int jb = half * 50;
        const float* w2p = W2 + (size_t)jb*FSZ + tl;
        float a0 = 0.f, a1 = 0.f;
        #pragma unroll
        for (int j = 0; j < 50; j += 2) {
            a0 = fmaf(s_h[jb+j],   w2p[(size_t)j*FSZ],     a0);
            a1 = fmaf(s_h[jb+j+1], w2p[(size_t)(j+1)*FSZ], a1);
        }
        s_acc[t] = a0 + a1;
    }
    __syncthreads();

    // combine halves, tanh, Womg reduction (threads 0..255 = warps 0..7)
    if (t < 256) {
        float fs = tanhf(b2[t] + s_acc[t] + s_acc[t + 256]);
        float p0 = fs * W[t*3+0];
        float p1 = fs * W[t*3+1];
        float p2 = fs * W[t*3+2];
        p0 = warp_sum(p0); p1 = warp_sum(p1); p2 = warp_sum(p2);
        int lane = t & 31, warp = t >> 5;
        if (lane == 0) {
            s_red[warp][0] = p0; s_red[warp][1] = p1; s_red[warp][2] = p2;
        }
    }
    __syncthreads();
    if (t < 3) {
        float v = 0.f;
        #pragma unroll
        for (int w = 0; w < 8; w++) v += s_red[w][t];
        g_Womg[f*3 + t] = v;
    }
}

// ---------------- Pass A: per-S-chunk trig totals ----------------
// 512 threads = all NF features; grid (NSC, BB).

__global__ void __launch_bounds__(512) k_passA(const float* __restrict__ X) {
    int t  = threadIdx.x;            // n = t
    int sc = blockIdx.x, b = blockIdx.y;
    float w0 = g_Womg[t*3+0], w1 = g_Womg[t*3+1], w2 = g_Womg[t*3+2];

    __shared__ float sx[SCH*3];
    int s0 = sc*SCH;
    const float* xp = X + ((size_t)b*SS + s0)*3;
    if (t < SCH*3) sx[t] = xp[t];
    __syncthreads();

    float sumC = 0.f, sumS = 0.f;
    #pragma unroll 8
    for (int k = 0; k < SCH; k++) {
        float th = fmaf(sx[k*3+2], w2, fmaf(sx[k*3+1], w1, sx[k*3]*w0));
        float sv, cv;
        __sincosf(th, &sv, &cv);
        sumC += cv; sumS += sv;
    }
    g_totC[(b*NSC + sc)*NF + t] = sumC;
    g_totS[(b*NSC + sc)*NF + t] = sumS;
}

// ---------------- Pass C fused with final output ----------------
// Same grid/block as passA. All 16 warp-partials per step stay in smem;
// block reduces them and writes lam + loglik directly.

__global__ void __launch_bounds__(512) k_passCF(const float* __restrict__ X,
                                                const float* __restrict__ alpha,
                                                float* __restrict__ out) {
    int t  = threadIdx.x;            // n = t
    int sc = blockIdx.x, b = blockIdx.y;
    float w0 = g_Womg[t*3+0], w1 = g_Womg[t*3+1], w2 = g_Womg[t*3+2];

    // exclusive offsets from preceding S chunks
    float runC = 0.f, runS = 0.f;
    for (int p = 0; p < sc; p++) {
        runC += g_totC[(b*NSC + p)*NF + t];
        runS += g_totS[(b*NSC + p)*NF + t];
    }

    __shared__ float sx[SCH*3];
    __shared__ float s_red[SCH][17];   // +1 pad: conflict-free tail reads
    int s0 = sc*SCH;
    const float* xp = X + ((size_t)b*SS + s0)*3;
    if (t < SCH*3) sx[t] = xp[t];
    __syncthreads();

    int lane = t & 31, warp = t >> 5;

    #pragma unroll 4
    for (int k = 0; k < SCH; k++) {
        float th = fmaf(sx[k*3+2], w2, fmaf(sx[k*3+1], w1, sx[k*3]*w0));
        float sv, cv;
        __sincosf(th, &sv, &cv);
        float contrib = cv*runC + sv*runS;   // EXCLUSIVE prefix
        runC += cv; runS += sv;
        contrib = warp_sum(contrib);
        if (lane == 0) s_red[k][warp] = contrib;
    }
    __syncthreads();

    if (t < SCH) {
        float s = 0.f;
        #pragma unroll
        for (int i = 0; i < 16; i++) s += s_red[t][i];
        float lam = fmaf(alpha[0], s * (1.0f/NF), 10.0f);
        int sg = s0 + t;
        out[b*SS + sg] = lam;

        float x0 = sx[t*3];
        float mask = (x0 > 0.f) ? 1.f : 0.f;
        const float C2 = -3947.8417604357433f;   // -MU*T*(2*pi)^(D-1)
        out[BB*SS + b*(SS+1) + sg] = logf(lam)*mask + C2;
    }
    if (sc == 0 && t == 0) {
        const float C2 = -3947.8417604357433f;
        out[BB*SS + b*(SS+1) + SS] = C2;         // extra (S+1)-th column
    }
}

// ---------------- Launch ----------------

extern "C" void kernel_launch(void* const* d_in, const int* in_sizes, int n_in,
                              void* d_out, int out_size) {
    const float* X     = (const float*)d_in[0];
    const float* noise = (const float*)d_in[1];
    const float* W1    = (const float*)d_in[2];
    const float* b1    = (const float*)d_in[3];
    const float* W2    = (const float*)d_in[4];
    const float* b2    = (const float*)d_in[5];
    const float* W     = (const float*)d_in[6];
    const float* alpha = (const float*)d_in[7];
    float* out = (float*)d_out;

    k_mlp<<<NF, 512>>>(noise, W1, b1, W2, b2, W);

    dim3 grid(NSC, BB);
    k_passA <<<grid, 512>>>(X);
    k_passCF<<<grid, 512>>>(X, alpha, out);
}

// round 14
// speedup vs baseline: 1.1222x; 1.1157x over previous
#include <cuda_runtime.h>
#include <math.h>

// Problem constants
#define BB   32
#define SS   1024
#define DD   3
#define NF   512
#define NS   64
#define HID  100
#define FSZ  256

// Decomposition
#define NSC  16           // S chunks
#define SCH  (SS/NSC)     // 64 steps per chunk

// Scratch (device globals: allocation-free per harness rules)
__device__ float g_Womg[NF*3];
__device__ float g_totC[BB*NSC*NF];
__device__ float g_totS[BB*NSC*NF];

// Warp-wide float add reduction (SHFL butterfly; redux.f32 unavailable on
// the compute_103 PTX target).
__device__ __forceinline__ float warp_sum(float v) {
    #pragma unroll
    for (int o = 16; o; o >>= 1) v += __shfl_xor_sync(0xffffffffu, v, o);
    return v;
}

// ---------------- Fused Fourier-feature MLP ----------------
// FROZEN at R11 configuration: measured 12.7us, the best of four structural
// variants (R9 13.2 / R12 20.1 / R13 13.7). Counters show it is neither
// traffic- nor occupancy- nor register-ILP-bound; without instruction-level
// stall data, further changes here are gambling. Do not touch.

__global__ void __launch_bounds__(512) k_mlp(const float* __restrict__ noise,
                                             const float* __restrict__ W1,
                                             const float* __restrict__ b1,
                                             const float* __restrict__ W2,
                                             const float* __restrict__ b2,
                                             const float* __restrict__ W) {
    int f = blockIdx.x;
    int t = threadIdx.x;
    int tl   = t & 255;      // col / hidden-unit id
    int half = t >> 8;       // 0 or 1: which j/k half this thread owns

    __shared__ float s_noise[NS];
    __shared__ float s_hp[2][HID];    // hidden k-partials
    __shared__ float s_h[HID];
    __shared__ float s_acc[512];      // fourier j-partials
    __shared__ float s_red[8][3];

    if (t < NS) s_noise[t] = noise[f*NS + t];
    __syncthreads();

    // hidden partials: h[j] over k in [half*32, half*32+32)
    if (tl < HID) {
        int k0 = half * 32;
        float a0 = 0.f, a1 = 0.f;
        #pragma unroll 8
        for (int k = 0; k < 32; k += 2) {
            a0 = fmaf(s_noise[k0+k],   W1[(k0+k)*HID + tl],   a0);
            a1 = fmaf(s_noise[k0+k+1], W1[(k0+k+1)*HID + tl], a1);
        }
        s_hp[half][tl] = a0 + a1;
    }
    __syncthreads();
    if (t < HID)
        s_h[t] = tanhf(b1[t] + s_hp[0][t] + s_hp[1][t]);
    __syncthreads();

    // fourier partials: col = tl, j in [half*50, half*50+50)
    {
        int jb = half * 50;
        float a0 = 0.f, a1 = 0.f;
        #pragma unroll 5
        for (int j = 0; j < 50; j += 2) {
            a0 = fmaf(s_h[jb+j],   W2[(jb+j)*FSZ + tl],   a0);
            a1 = fmaf(s_h[jb+j+1], W2[(jb+j+1)*FSZ + tl], a1);
        }
        s_acc[t] = a0 + a1;
    }
    __syncthreads();

    // combine halves, tanh, Womg reduction (threads 0..255 = warps 0..7)
    if (t < 256) {
        float fs = tanhf(b2[t] + s_acc[t] + s_acc[t + 256]);
        float p0 = fs * W[t*3+0];
        float p1 = fs * W[t*3+1];
        float p2 = fs * W[t*3+2];
        p0 = warp_sum(p0); p1 = warp_sum(p1); p2 = warp_sum(p2);
        int lane = t & 31, warp = t >> 5;
        if (lane == 0) {
            s_red[warp][0] = p0; s_red[warp][1] = p1; s_red[warp][2] = p2;
        }
    }
    __syncthreads();
    if (t < 3) {
        float v = 0.f;
        #pragma unroll
        for (int w = 0; w < 8; w++) v += s_red[w][t];
        g_Womg[f*3 + t] = v;
    }
}

// ---------------- Pass A: per-S-chunk trig totals ----------------
// 512 threads = all NF features; grid (NSC, BB).

__global__ void __launch_bounds__(512) k_passA(const float* __restrict__ X) {
    int t  = threadIdx.x;            // n = t
    int sc = blockIdx.x, b = blockIdx.y;
    float w0 = g_Womg[t*3+0], w1 = g_Womg[t*3+1], w2 = g_Womg[t*3+2];

    __shared__ float sx[SCH*3];
    int s0 = sc*SCH;
    const float* xp = X + ((size_t)b*SS + s0)*3;
    if (t < SCH*3) sx[t] = xp[t];
    __syncthreads();

    float sumC = 0.f, sumS = 0.f;
    #pragma unroll 8
    for (int k = 0; k < SCH; k++) {
        float th = fmaf(sx[k*3+2], w2, fmaf(sx[k*3+1], w1, sx[k*3]*w0));
        float sv, cv;
        __sincosf(th, &sv, &cv);
        sumC += cv; sumS += sv;
    }
    g_totC[(b*NSC + sc)*NF + t] = sumC;
    g_totS[(b*NSC + sc)*NF + t] = sumS;
}

// ---------------- Pass C fused with final output ----------------
// Per-step reduction shortened: 2-level SHFL butterfly (xor16, xor8) leaves
// the 8 group-of-4 sums in lanes 0..7; those are stored to s_red[k][...]
// (129-padded, conflict-free) and a single block-wide tail reduces 128
// partials per step. Saves ~6 issued instr per thread-step vs the full
// 5-level butterfly.

#define RPAD 129   // row stride of s_red (odd => conflict-free strided reads)

__global__ void __launch_bounds__(512) k_passCF(const float* __restrict__ X,
                                                const float* __restrict__ alpha,
                                                float* __restrict__ out) {
    int t  = threadIdx.x;            // n = t
    int sc = blockIdx.x, b = blockIdx.y;
    float w0 = g_Womg[t*3+0], w1 = g_Womg[t*3+1], w2 = g_Womg[t*3+2];

    // exclusive offsets from preceding S chunks
    float runC = 0.f, runS = 0.f;
    for (int p = 0; p < sc; p++) {
        runC += g_totC[(b*NSC + p)*NF + t];
        runS += g_totS[(b*NSC + p)*NF + t];
    }

    __shared__ float sx[SCH*3];
    __shared__ float s_red[SCH*RPAD]; // [SCH][129], 33KB static
    int s0 = sc*SCH;
    const float* xp = X + ((size_t)b*SS + s0)*3;
    if (t < SCH*3) sx[t] = xp[t];
    __syncthreads();

    int lane = t & 31, warp = t >> 5;
    int g8   = lane & 7;              // group id within warp after 2 levels
    int wr   = warp*8 + g8;           // partial column 0..127

    #pragma unroll 4
    for (int k = 0; k < SCH; k++) {
        float th = fmaf(sx[k*3+2], w2, fmaf(sx[k*3+1], w1, sx[k*3]*w0));
        float sv, cv;
        __sincosf(th, &sv, &cv);
        float contrib = cv*runC + sv*runS;   // EXCLUSIVE prefix
        runC += cv; runS += sv;
        // 2-level butterfly: lane l ends with sum over {l, l^8, l^16, l^24}
        contrib += __shfl_xor_sync(0xffffffffu, contrib, 16);
        contrib += __shfl_xor_sync(0xffffffffu, contrib, 8);
        if (lane < 8) s_red[k*RPAD + wr] = contrib;
    }
    __syncthreads();

    // Tail: 8 threads per k (t>>3 = k, t&7 = j) sum 16 strided partials,
    // then 3-level shfl within the 8-thread group.
    {
        int k = t >> 3, j = t & 7;
        const float* row = s_red + k*RPAD;
        float s = 0.f;
        #pragma unroll
        for (int i = 0; i < 16; i++) s += row[j + 8*i];
        s += __shfl_xor_sync(0xffffffffu, s, 4);
        s += __shfl_xor_sync(0xffffffffu, s, 2);
        s += __shfl_xor_sync(0xffffffffu, s, 1);
        if (j == 0) {
            float lam = fmaf(alpha[0], s * (1.0f/NF), 10.0f);
            int sg = s0 + k;
            out[b*SS + sg] = lam;
            float x0 = sx[k*3];
            float mask = (x0 > 0.f) ? 1.f : 0.f;
            const float C2 = -3947.8417604357433f;   // -MU*T*(2*pi)^(D-1)
            out[BB*SS + b*(SS+1) + sg] = logf(lam)*mask + C2;
        }
    }
    if (sc == 0 && t == 0) {
        const float C2 = -3947.8417604357433f;
        out[BB*SS + b*(SS+1) + SS] = C2;         // extra (S+1)-th column
    }
}

// ---------------- Launch ----------------

extern "C" void kernel_launch(void* const* d_in, const int* in_sizes, int n_in,
                              void* d_out, int out_size) {
    const float* X     = (const float*)d_in[0];
    const float* noise = (const float*)d_in[1];
    const float* W1    = (const float*)d_in[2];
    const float* b1    = (const float*)d_in[3];
    const float* W2    = (const float*)d_in[4];
    const float* b2    = (const float*)d_in[5];
    const float* W     = (const float*)d_in[6];
    const float* alpha = (const float*)d_in[7];
    float* out = (float*)d_out;

    k_mlp<<<NF, 512>>>(noise, W1, b1, W2, b2, W);

    dim3 grid(NSC, BB);
    k_passA <<<grid, 512>>>(X);
    k_passCF<<<grid, 512>>>(X, alpha, out);
}

// round 15
// speedup vs baseline: 1.1712x; 1.0437x over previous
#include <cuda_runtime.h>
#include <math.h>

// Problem constants
#define BB   32
#define SS   1024
#define DD   3
#define NF   512
#define NS   64
#define HID  100
#define FSZ  256

// Decomposition
#define NSC  16           // S chunks
#define SCH  (SS/NSC)     // 64 steps per chunk

// Scratch (device globals: allocation-free per harness rules)
__device__ float g_Womg[NF*3];
__device__ float g_totC[BB*NSC*NF];
__device__ float g_totS[BB*NSC*NF];

// Warp-wide float add reduction (SHFL butterfly; redux.f32 unavailable on
// the compute_103 PTX target).
__device__ __forceinline__ float warp_sum(float v) {
    #pragma unroll
    for (int o = 16; o; o >>= 1) v += __shfl_xor_sync(0xffffffffu, v, o);
    return v;
}

// ---------------- Fused Fourier-feature MLP ----------------
// R14 analysis: LSU-issue bound. 50 scalar LDG.32 of W2 per thread = 800
// warp-LDG per block at the 4cyc LDG->LDG structural floor ~= 5.6us/SM of
// pure load issue. Fix: thread owns a 4-column quad -> one LDG.128 per
// (j, quad) + 4 FMAs; W2 warp-LDG count drops 800 -> 208 per block and the
// W2-path LDS stream disappears entirely.

#define APAD 260   // row stride of s_accp: %32==4 -> combine reads hit
                   // distinct banks; %4==0 -> float4 stores stay aligned

__global__ void __launch_bounds__(512) k_mlp(const float* __restrict__ noise,
                                             const float* __restrict__ W1,
                                             const float* __restrict__ b1,
                                             const float* __restrict__ W2,
                                             const float* __restrict__ b2,
                                             const float* __restrict__ W) {
    int f = blockIdx.x;
    int t = threadIdx.x;
    int tl   = t & 255;      // hidden-unit id
    int half = t >> 8;       // 0 or 1: which k half (hidden phase)

    __shared__ float s_noise[NS];
    __shared__ float s_hp[2][HID];     // hidden k-partials
    __shared__ float s_h[HID];
    __shared__ float s_accp[8*APAD];   // fourier j-group partials
    __shared__ float s_red[8][3];

    if (t < NS) s_noise[t] = noise[f*NS + t];
    __syncthreads();

    // hidden partials: h[j] over k in [half*32, half*32+32)
    if (tl < HID) {
        int k0 = half * 32;
        float a0 = 0.f, a1 = 0.f;
        #pragma unroll 8
        for (int k = 0; k < 32; k += 2) {
            a0 = fmaf(s_noise[k0+k],   W1[(k0+k)*HID + tl],   a0);
            a1 = fmaf(s_noise[k0+k+1], W1[(k0+k+1)*HID + tl], a1);
        }
        s_hp[half][tl] = a0 + a1;
    }
    __syncthreads();
    if (t < HID)
        s_h[t] = tanhf(b1[t] + s_hp[0][t] + s_hp[1][t]);
    __syncthreads();

    // fourier: thread -> (column quad q4, j-group g). One LDG.128 + 4 FMAs
    // per iteration; ~13 iterations per thread.
    {
        int q4 = (t & 63) * 4;
        int g  = t >> 6;                 // 0..7
        int j0 = g * 13;
        int j1 = (j0 + 13 < HID) ? j0 + 13 : HID;
        float ax = 0.f, ay = 0.f, az = 0.f, aw = 0.f;
        for (int j = j0; j < j1; j++) {
            float4 w = *reinterpret_cast<const float4*>(W2 + (size_t)j*FSZ + q4);
            float h = s_h[j];
            ax = fmaf(h, w.x, ax);
            ay = fmaf(h, w.y, ay);
            az = fmaf(h, w.z, az);
            aw = fmaf(h, w.w, aw);
        }
        float4 o; o.x = ax; o.y = ay; o.z = az; o.w = aw;
        *reinterpret_cast<float4*>(&s_accp[g*APAD + q4]) = o;
    }
    __syncthreads();

    // combine 8 j-groups per column, tanh, Womg reduction (warps 0..7)
    if (t < 256) {
        float a = 0.f;
        #pragma unroll
        for (int g = 0; g < 8; g++) a += s_accp[g*APAD + t];
        float fs = tanhf(b2[t] + a);
        float p0 = fs * W[t*3+0];
        float p1 = fs * W[t*3+1];
        float p2 = fs * W[t*3+2];
        p0 = warp_sum(p0); p1 = warp_sum(p1); p2 = warp_sum(p2);
        int lane = t & 31, warp = t >> 5;
        if (lane == 0) {
            s_red[warp][0] = p0; s_red[warp][1] = p1; s_red[warp][2] = p2;
        }
    }
    __syncthreads();
    if (t < 3) {
        float v = 0.f;
        #pragma unroll
        for (int w = 0; w < 8; w++) v += s_red[w][t];
        g_Womg[f*3 + t] = v;
    }
}

// ---------------- Pass A: per-S-chunk trig totals ----------------
// 512 threads = all NF features; grid (NSC, BB).

__global__ void __launch_bounds__(512) k_passA(const float* __restrict__ X) {
    int t  = threadIdx.x;            // n = t
    int sc = blockIdx.x, b = blockIdx.y;
    float w0 = g_Womg[t*3+0], w1 = g_Womg[t*3+1], w2 = g_Womg[t*3+2];

    __shared__ float sx[SCH*3];
    int s0 = sc*SCH;
    const float* xp = X + ((size_t)b*SS + s0)*3;
    if (t < SCH*3) sx[t] = xp[t];
    __syncthreads();

    float sumC = 0.f, sumS = 0.f;
    #pragma unroll 8
    for (int k = 0; k < SCH; k++) {
        float th = fmaf(sx[k*3+2], w2, fmaf(sx[k*3+1], w1, sx[k*3]*w0));
        float sv, cv;
        __sincosf(th, &sv, &cv);
        sumC += cv; sumS += sv;
    }
    g_totC[(b*NSC + sc)*NF + t] = sumC;
    g_totS[(b*NSC + sc)*NF + t] = sumS;
}

// ---------------- Pass C fused with final output ----------------
// 2-level SHFL butterfly + padded smem partials + block tail (R14-proven).

#define RPAD 129   // row stride of s_red (odd => conflict-free strided reads)

__global__ void __launch_bounds__(512) k_passCF(const float* __restrict__ X,
                                                const float* __restrict__ alpha,
                                                float* __restrict__ out) {
    int t  = threadIdx.x;            // n = t
    int sc = blockIdx.x, b = blockIdx.y;
    float w0 = g_Womg[t*3+0], w1 = g_Womg[t*3+1], w2 = g_Womg[t*3+2];

    // exclusive offsets from preceding S chunks
    float runC = 0.f, runS = 0.f;
    for (int p = 0; p < sc; p++) {
        runC += g_totC[(b*NSC + p)*NF + t];
        runS += g_totS[(b*NSC + p)*NF + t];
    }

    __shared__ float sx[SCH*3];
    __shared__ float s_red[SCH*RPAD]; // [SCH][129], 33KB static
    int s0 = sc*SCH;
    const float* xp = X + ((size_t)b*SS + s0)*3;
    if (t < SCH*3) sx[t] = xp[t];
    __syncthreads();

    int lane = t & 31, warp = t >> 5;
    int g8   = lane & 7;              // group id within warp after 2 levels
    int wr   = warp*8 + g8;           // partial column 0..127

    #pragma unroll 4
    for (int k = 0; k < SCH; k++) {
        float th = fmaf(sx[k*3+2], w2, fmaf(sx[k*3+1], w1, sx[k*3]*w0));
        float sv, cv;
        __sincosf(th, &sv, &cv);
        float contrib = cv*runC + sv*runS;   // EXCLUSIVE prefix
        runC += cv; runS += sv;
        // 2-level butterfly: lane l ends with sum over {l, l^8, l^16, l^24}
        contrib += __shfl_xor_sync(0xffffffffu, contrib, 16);
        contrib += __shfl_xor_sync(0xffffffffu, contrib, 8);
        if (lane < 8) s_red[k*RPAD + wr] = contrib;
    }
    __syncthreads();

    // Tail: 8 threads per k (t>>3 = k, t&7 = j) sum 16 strided partials,
    // then 3-level shfl within the 8-thread group.
    {
        int k = t >> 3, j = t & 7;
        const float* row = s_red + k*RPAD;
        float s = 0.f;
        #pragma unroll
        for (int i = 0; i < 16; i++) s += row[j + 8*i];
        s += __shfl_xor_sync(0xffffffffu, s, 4);
        s += __shfl_xor_sync(0xffffffffu, s, 2);
        s += __shfl_xor_sync(0xffffffffu, s, 1);
        if (j == 0) {
            float lam = fmaf(alpha[0], s * (1.0f/NF), 10.0f);
            int sg = s0 + k;
            out[b*SS + sg] = lam;
            float x0 = sx[k*3];
            float mask = (x0 > 0.f) ? 1.f : 0.f;
            const float C2 = -3947.8417604357433f;   // -MU*T*(2*pi)^(D-1)
            out[BB*SS + b*(SS+1) + sg] = logf(lam)*mask + C2;
        }
    }
    if (sc == 0 && t == 0) {
        const float C2 = -3947.8417604357433f;
        out[BB*SS + b*(SS+1) + SS] = C2;         // extra (S+1)-th column
    }
}

// ---------------- Launch ----------------

extern "C" void kernel_launch(void* const* d_in, const int* in_sizes, int n_in,
                              void* d_out, int out_size) {
    const float* X     = (const float*)d_in[0];
    const float* noise = (const float*)d_in[1];
    const float* W1    = (const float*)d_in[2];
    const float* b1    = (const float*)d_in[3];
    const float* W2    = (const float*)d_in[4];
    const float* b2    = (const float*)d_in[5];
    const float* W     = (const float*)d_in[6];
    const float* alpha = (const float*)d_in[7];
    float* out = (float*)d_out;

    k_mlp<<<NF, 512>>>(noise, W1, b1, W2, b2, W);

    dim3 grid(NSC, BB);
    k_passA <<<grid, 512>>>(X);
    k_passCF<<<grid, 512>>>(X, alpha, out);
}